// round 7
// baseline (speedup 1.0000x reference)
#include <cuda_runtime.h>
#include <math.h>

#define N_TOT 4096
#define C_DIM 256
#define K_NEG 128
#define HW 1024
#define INV_T (1.0f / 0.07f)
#define Q8 256.0f                        // int8 quant scale for both q and k
#define NEG_SCALE (INV_T / (Q8 * Q8))    // logit scale for int dots
#define NEG_INF (-1e30f)
#define FIX_SCALE 4294967296.0           // 2^32

// Scratch (allocation-free rule: __device__ globals)
__device__ __align__(16) signed char g_qn8[N_TOT * C_DIM]; // q int8*256
__device__ __align__(16) signed char g_kn8[N_TOT * C_DIM]; // k int8*256
__device__ float g_lpos[N_TOT];                             // l_pos logit (fp32)
__device__ unsigned long long g_acc;                        // fixed-point loss sum
__device__ unsigned int       g_done;                       // block completion ctr

__device__ __forceinline__ signed char q8(float v) {
    int iv = __float2int_rn(v * Q8);
    iv = max(-127, min(127, iv));
    return (signed char)iv;
}
__device__ __forceinline__ void cp16(void* smem_dst, const void* gmem_src) {
    unsigned d = (unsigned)__cvta_generic_to_shared(smem_dst);
    asm volatile("cp.async.ca.shared.global [%0], [%1], 16;\n"
                 :: "r"(d), "l"(gmem_src) : "memory");
}

// ---------------------------------------------------------------------------
// Kernel 1: normalize q,k over C, transpose [B,C,HW] -> [N,C] int8, and
// compute l_pos = (qn . kn) / T in fp32. grid = 512 tiles of 8, block (8,32).
// ---------------------------------------------------------------------------
__global__ void __launch_bounds__(256) norm_transpose_kernel(
    const float* __restrict__ fq, const float* __restrict__ fk)
{
    if (blockIdx.x == 0 && threadIdx.x == 0 && threadIdx.y == 0)
        g_acc = 0ull;

    const int n0  = blockIdx.x * 8;       // 8 | 1024, tile never crosses batch
    const int b   = n0 / HW;
    const int hw0 = n0 % HW;
    const int tx  = threadIdx.x;          // 0..7  : hw within tile
    const int ty  = threadIdx.y;          // 0..31 : channel group

    __shared__ float tq[C_DIM][9];
    __shared__ float tk[C_DIM][9];
    __shared__ float ssq[32][8], ssk[32][8], sdt[32][8];
    __shared__ float sinvq[8], sinvk[8];

    const size_t boff = (size_t)b * C_DIM * HW + hw0 + tx;
    const float* bq = fq + boff;
    const float* bk = fk + boff;

    float aq = 0.f, ak = 0.f, ad = 0.f;
    #pragma unroll
    for (int cc = 0; cc < 8; cc++) {
        int c = cc * 32 + ty;
        float vq = bq[(size_t)c * HW];
        float vk = bk[(size_t)c * HW];
        tq[c][tx] = vq;
        tk[c][tx] = vk;
        aq += vq * vq;
        ak += vk * vk;
        ad += vq * vk;
    }
    ssq[ty][tx] = aq;
    ssk[ty][tx] = ak;
    sdt[ty][tx] = ad;
    __syncthreads();

    if (ty == 0) {
        float sq = 0.f, sk = 0.f, sd = 0.f;
        #pragma unroll
        for (int r = 0; r < 32; r++) {
            sq += ssq[r][tx];
            sk += ssk[r][tx];
            sd += sdt[r][tx];
        }
        float iq = rsqrtf(fmaxf(sq, 1e-24f));
        float ik = rsqrtf(fmaxf(sk, 1e-24f));
        sinvq[tx] = iq;
        sinvk[tx] = ik;
        g_lpos[n0 + tx] = sd * iq * ik * INV_T;
    }
    __syncthreads();

    const int c = ty * 8 + tx;            // thread owns one channel
    #pragma unroll
    for (int r = 0; r < 8; r++) {
        size_t o = (size_t)(n0 + r) * C_DIM + c;
        g_qn8[o] = q8(tq[c][r] * sinvq[r]);
        g_kn8[o] = q8(tk[c][r] * sinvk[r]);
    }
}

// ---------------------------------------------------------------------------
// Kernel 2: gather 128 k-rows/block into smem via cp.async (16 lanes/row,
// coalesced), then lane-per-negative int8 dp4a from smem (no reductions),
// logsumexp + fused final mean. One block (128 thr) per position n.
// ---------------------------------------------------------------------------
__global__ void __launch_bounds__(128) patchnce_main_kernel(
    const int* __restrict__ negs, float* __restrict__ out)
{
    const int n    = blockIdx.x;
    const int tid  = threadIdx.x;
    const int lane = tid & 31;
    const int warp = tid >> 5;
    const int half = lane >> 4;           // 0/1: which row of the staged pair
    const int hl   = lane & 15;           // lane within half

    __shared__ uint4 sk[K_NEG][17];       // gathered k rows, 272B stride (pad)
    __shared__ uint4 sq[4][16];           // per-warp q row copy (broadcast reads)
    __shared__ float slog[132];           // 129 logits (0 = l_pos)
    __shared__ float red[4];

    const char* __restrict__ kbytes = (const char*)g_kn8;

    if (tid == 0) slog[0] = g_lpos[n];

    // per-lane negative index (lane l of warp w owns negative w*32+l)
    int myidx = negs[(size_t)n * K_NEG + warp * 32 + lane];
    myidx += (myidx >= n) ? 1 : 0;        // self-exclusion shift

    // stage q (16 lanes) — per-warp private copy, no block sync needed
    if (lane < 16)
        cp16(&sq[warp][lane], g_qn8 + (size_t)n * C_DIM + lane * 16);

    // stage this warp's 32 k rows: 2 rows per instruction, 16 lanes per row
    #pragma unroll
    for (int j = 0; j < 16; j++) {
        const int r   = (j << 1) | half;                  // row within warp
        const int idx = __shfl_sync(0xffffffffu, myidx, r);
        cp16(&sk[warp * 32 + r][hl],
             kbytes + (size_t)idx * C_DIM + hl * 16);
    }
    asm volatile("cp.async.commit_group;\n" ::: "memory");
    asm volatile("cp.async.wait_group 0;\n" ::: "memory");
    __syncwarp();

    // lane-per-negative dot from smem: 16 x (LDS.128 k + LDS.128 q + 4 DP4A)
    {
        const uint4* krow = sk[warp * 32 + lane];
        int d = 0;
        #pragma unroll
        for (int c = 0; c < 16; c++) {
            uint4 kv = krow[c];           // conflict-free: banks 4(l+c) mod 32
            uint4 qv = sq[warp][c];       // broadcast
            d = __dp4a((int)kv.x, (int)qv.x, d);
            d = __dp4a((int)kv.y, (int)qv.y, d);
            d = __dp4a((int)kv.z, (int)qv.z, d);
            d = __dp4a((int)kv.w, (int)qv.w, d);
        }
        slog[1 + warp * 32 + lane] = (float)d * NEG_SCALE;
    }
    __syncthreads();

    // logsumexp over 129 logits (thread 0 also covers slog[128])
    const float x     = slog[tid];
    const float extra = (tid == 0) ? slog[128] : NEG_INF;

    float mx = fmaxf(x, extra);
    #pragma unroll
    for (int o = 16; o > 0; o >>= 1)
        mx = fmaxf(mx, __shfl_xor_sync(0xffffffffu, mx, o));
    if (lane == 0) red[warp] = mx;
    __syncthreads();
    mx = fmaxf(fmaxf(red[0], red[1]), fmaxf(red[2], red[3]));
    __syncthreads();                      // WAR on red[]

    float e = expf(x - mx) + ((tid == 0) ? expf(extra - mx) : 0.f);
    #pragma unroll
    for (int o = 16; o > 0; o >>= 1) e += __shfl_xor_sync(0xffffffffu, e, o);
    if (lane == 0) red[warp] = e;
    __syncthreads();

    if (tid == 0) {
        float s = red[0] + red[1] + red[2] + red[3];
        float rowloss = mx + logf(s) - slog[0];   // >= 0 always
        unsigned long long fx =
            (unsigned long long)llrintf(rowloss * (float)FIX_SCALE);
        atomicAdd(&g_acc, fx);            // integer atomics commute: deterministic
        __threadfence();
        unsigned int t = atomicAdd(&g_done, 1u);
        if (t == (unsigned int)(gridDim.x - 1)) {
            unsigned long long total = atomicAdd(&g_acc, 0ull);
            out[0] = (float)((double)total * (1.0 / FIX_SCALE) * (1.0 / N_TOT));
            g_done = 0u;                  // reset for next graph replay
        }
    }
}

// ---------------------------------------------------------------------------
extern "C" void kernel_launch(void* const* d_in, const int* in_sizes, int n_in,
                              void* d_out, int out_size)
{
    const float* fq   = (const float*)d_in[0];
    const float* fk   = (const float*)d_in[1];
    const int*   negs = (const int*)d_in[2];
    float*       out  = (float*)d_out;

    norm_transpose_kernel<<<512, dim3(8, 32)>>>(fq, fk);
    patchnce_main_kernel<<<N_TOT, 128>>>(negs, out);
}